// round 10
// baseline (speedup 1.0000x reference)
#include <cuda_runtime.h>
#include <cuda_fp16.h>

#define HIDDEN    256
#define NUM_HEADS 8
#define HEAD_DIM  32
#define MAX_N     20000
#define MAX_E     320000
#define MAX_DEG   128
#define KV_ROW    512                      /* 256 k-halves + 256 v-halves */
#define INV_SCALE 0.17677669529663687f     /* 1/sqrt(32) */

// Scratch (alloc-free rule: __device__ globals)
__device__ int            g_cnt[MAX_N];              // per-node fill cursor / degree
__device__ unsigned short g_srcs[MAX_N * MAX_DEG];   // bucketed adjacency (src < 65536)
__device__ __half         g_kv[MAX_N * KV_ROW];      // interleaved fp16 [k-row | v-row]
__device__ int            g_idx32;                   // 1 if edge_index is int32

// ---------------------------------------------------------------- A: zero cursors + dtype detect
__global__ void ca_zero_kernel(const long long* __restrict__ ei, int N, int E) {
    // dtype probe in block 0: int64 data has all values in [0,N); int32 misread
    // as int64 packs two indices and lands out of range w.h.p.
    if (blockIdx.x == 0) {
        int i = threadIdx.x;
        int nsample = E < 256 ? E : 256;
        int bad = 0;
        if (i < nsample) {
            long long x = ei[i];
            bad = (x < 0 || x >= (long long)N) ? 1 : 0;
        }
        int any = __syncthreads_or(bad);
        if (i == 0) g_idx32 = any;
    }
    int t = blockIdx.x * blockDim.x + threadIdx.x;
    int i4 = t * 4;
    if (i4 + 3 < N) {
        *(int4*)&g_cnt[i4] = make_int4(0, 0, 0, 0);
    } else {
        for (int i = i4; i < N; ++i) g_cnt[i] = 0;
    }
}

// ---------------------------------------------------------------- B: fused convert + scatter
// Blocks [0, conv_blocks): fp16 convert of k,v into interleaved g_kv.
// Blocks [conv_blocks, ...): edge scatter, 4 edges/thread.
// Scatter's atomic latency hides under convert's HBM stalls.
__global__ void ca_prep_kernel(const float* __restrict__ k,
                               const float* __restrict__ v,
                               const void* __restrict__ ei_raw,
                               int total8 /* N*HIDDEN/8 */, int N, int E,
                               int conv_blocks) {
    if (blockIdx.x < (unsigned)conv_blocks) {
        // ---- convert role ----
        int t = blockIdx.x * blockDim.x + threadIdx.x;
        if (t >= total8) return;
        int p    = t * 8;                 // linear float index into k / v
        int node = p >> 8;                // / HIDDEN
        int idx  = p & (HIDDEN - 1);

        float4 ka = *(const float4*)(k + p);
        float4 kb = *(const float4*)(k + p + 4);
        float4 va = *(const float4*)(v + p);
        float4 vb = *(const float4*)(v + p + 4);

        __half2 kh[4], vh[4];
        kh[0] = __floats2half2_rn(ka.x, ka.y);
        kh[1] = __floats2half2_rn(ka.z, ka.w);
        kh[2] = __floats2half2_rn(kb.x, kb.y);
        kh[3] = __floats2half2_rn(kb.z, kb.w);
        vh[0] = __floats2half2_rn(va.x, va.y);
        vh[1] = __floats2half2_rn(va.z, va.w);
        vh[2] = __floats2half2_rn(vb.x, vb.y);
        vh[3] = __floats2half2_rn(vb.z, vb.w);

        __half* row = g_kv + (size_t)node * KV_ROW;
        *(uint4*)(row + idx)          = *(const uint4*)kh;
        *(uint4*)(row + HIDDEN + idx) = *(const uint4*)vh;
    } else {
        // ---- scatter role: 4 edges/thread ----
        int sb   = blockIdx.x - conv_blocks;
        int base = (sb * blockDim.x + threadIdx.x) * 4;
        if (base >= E) return;
        int n = E - base; if (n > 4) n = 4;

        int src[4], dst[4];
        if (g_idx32) {
            const int* ei = (const int*)ei_raw;
            #pragma unroll
            for (int i = 0; i < 4; ++i) {
                if (i < n) { src[i] = ei[base + i]; dst[i] = ei[E + base + i]; }
            }
        } else {
            const long long* ei = (const long long*)ei_raw;
            #pragma unroll
            for (int i = 0; i < 4; ++i) {
                if (i < n) { src[i] = (int)ei[base + i]; dst[i] = (int)ei[E + base + i]; }
            }
        }
        #pragma unroll
        for (int i = 0; i < 4; ++i) {
            if (i < n &&
                (unsigned)src[i] < (unsigned)N && (unsigned)dst[i] < (unsigned)N) {
                int pos = atomicAdd(&g_cnt[dst[i]], 1);
                if (pos < MAX_DEG)
                    g_srcs[dst[i] * MAX_DEG + pos] = (unsigned short)src[i];
            }
        }
    }
}

// ---------------------------------------------------------------- per-edge fp16 math
__device__ __forceinline__ void ca_edge_math(uint4 kb, uint4 vb,
                                             float4 q0, float4 q1,
                                             float& a0, float& a1, float& a2, float& a3,
                                             float& a4, float& a5, float& a6, float& a7,
                                             float& zsum) {
    const __half2* kh = (const __half2*)&kb;
    const __half2* vh = (const __half2*)&vb;
    float2 k0 = __half22float2(kh[0]);
    float2 k1 = __half22float2(kh[1]);
    float2 k2 = __half22float2(kh[2]);
    float2 k3 = __half22float2(kh[3]);

    float d = k0.x*q0.x + k0.y*q0.y + k1.x*q0.z + k1.y*q0.w
            + k2.x*q1.x + k2.y*q1.y + k3.x*q1.z + k3.y*q1.w;
    d += __shfl_xor_sync(0xffffffffu, d, 1);
    d += __shfl_xor_sync(0xffffffffu, d, 2);

    float s = __expf(fminf(5.0f, fmaxf(-5.0f, d * INV_SCALE)));

    float2 v0 = __half22float2(vh[0]);
    float2 v1 = __half22float2(vh[1]);
    float2 v2 = __half22float2(vh[2]);
    float2 v3 = __half22float2(vh[3]);
    a0 += v0.x*s; a1 += v0.y*s; a2 += v1.x*s; a3 += v1.y*s;
    a4 += v2.x*s; a5 += v2.y*s; a6 += v3.x*s; a7 += v3.y*s;
    zsum += s;
}

// ---------------------------------------------------------------- C: gather + normalize (R9, unchanged)
__global__ void ca_gather_kernel(const float* __restrict__ q,
                                 float* __restrict__ out,
                                 int N) {
    int node = blockIdx.x * (blockDim.x >> 5) + (threadIdx.x >> 5);
    if (node >= N) return;
    int lane = threadIdx.x & 31;
    int head = lane >> 2;
    int sub  = lane & 3;
    int off  = head * HEAD_DIM + sub * 8;

    const float4* qp = (const float4*)(q + (size_t)node * HIDDEN + off);
    float4 q0 = qp[0], q1 = qp[1];

    float a0=0,a1=0,a2=0,a3=0,a4=0,a5=0,a6=0,a7=0;
    float zsum = 0.0f;

    int deg = g_cnt[node];
    if (deg > MAX_DEG) deg = MAX_DEG;
    const unsigned short* adj = &g_srcs[node * MAX_DEG];
    int j = 0;

    for (; j + 3 < deg; j += 4) {
        ushort4 s4 = *(const ushort4*)(adj + j);   // row base 256B-aligned, j%4==0
        const __half* r0 = g_kv + (size_t)s4.x * KV_ROW + off;
        const __half* r1 = g_kv + (size_t)s4.y * KV_ROW + off;
        const __half* r2 = g_kv + (size_t)s4.z * KV_ROW + off;
        const __half* r3 = g_kv + (size_t)s4.w * KV_ROW + off;
        uint4 kb0 = *(const uint4*)(r0);
        uint4 vb0 = *(const uint4*)(r0 + HIDDEN);
        uint4 kb1 = *(const uint4*)(r1);
        uint4 vb1 = *(const uint4*)(r1 + HIDDEN);
        uint4 kb2 = *(const uint4*)(r2);
        uint4 vb2 = *(const uint4*)(r2 + HIDDEN);
        uint4 kb3 = *(const uint4*)(r3);
        uint4 vb3 = *(const uint4*)(r3 + HIDDEN);

        ca_edge_math(kb0, vb0, q0, q1, a0,a1,a2,a3,a4,a5,a6,a7, zsum);
        ca_edge_math(kb1, vb1, q0, q1, a0,a1,a2,a3,a4,a5,a6,a7, zsum);
        ca_edge_math(kb2, vb2, q0, q1, a0,a1,a2,a3,a4,a5,a6,a7, zsum);
        ca_edge_math(kb3, vb3, q0, q1, a0,a1,a2,a3,a4,a5,a6,a7, zsum);
    }
    for (; j < deg; ++j) {
        int s = adj[j];
        const __half* r = g_kv + (size_t)s * KV_ROW + off;
        uint4 kb = *(const uint4*)(r);
        uint4 vb = *(const uint4*)(r + HIDDEN);
        ca_edge_math(kb, vb, q0, q1, a0,a1,a2,a3,a4,a5,a6,a7, zsum);
    }

    float zinv = 1.0f / (zsum + 1e-6f);
    float4 o0 = make_float4(a0*zinv, a1*zinv, a2*zinv, a3*zinv);
    float4 o1 = make_float4(a4*zinv, a5*zinv, a6*zinv, a7*zinv);
    float4* op = (float4*)(out + (size_t)node * HIDDEN + off);
    op[0] = o0;
    op[1] = o1;
}

extern "C" void kernel_launch(void* const* d_in, const int* in_sizes, int n_in,
                              void* d_out, int out_size) {
    const float* q  = (const float*)d_in[0];
    const float* k  = (const float*)d_in[1];
    const float* v  = (const float*)d_in[2];
    const void*  ei = d_in[3];
    float* out = (float*)d_out;

    int N = in_sizes[0] / HIDDEN;
    int E = in_sizes[3] / 2;

    // A: zero cursors + dtype detect
    {
        int t4 = (N + 3) / 4;
        ca_zero_kernel<<<(t4 + 255) / 256, 256>>>((const long long*)ei, N, E);
    }
    // B: fused convert + scatter
    {
        int total8      = N * HIDDEN / 8;
        int conv_blocks = (total8 + 255) / 256;
        int scat_thr    = (E + 3) / 4;
        int scat_blocks = (scat_thr + 255) / 256;
        ca_prep_kernel<<<conv_blocks + scat_blocks, 256>>>(k, v, ei,
                                                           total8, N, E, conv_blocks);
    }
    // C: gather + normalize
    {
        int warps_per_block = 8;
        int threads = warps_per_block * 32;
        int blocks = (N + warps_per_block - 1) / warps_per_block;
        ca_gather_kernel<<<blocks, threads>>>(q, out, N);
    }
}

// round 11
// speedup vs baseline: 1.0457x; 1.0457x over previous
#include <cuda_runtime.h>
#include <cuda_fp16.h>

#define HIDDEN    256
#define NUM_HEADS 8
#define HEAD_DIM  32
#define MAX_N     20000
#define MAX_E     320000
#define MAX_DEG   128
#define KV_ROW    512                      /* 256 k-halves + 256 v-halves */
#define INV_SCALE 0.17677669529663687f     /* 1/sqrt(32) */

// Scratch (alloc-free rule: __device__ globals)
__device__ int            g_cnt[MAX_N];              // per-node fill cursor / degree
__device__ unsigned short g_srcs[MAX_N * MAX_DEG];   // bucketed adjacency (src < 65536)
__device__ __half         g_kv[MAX_N * KV_ROW];      // interleaved fp16 [k-row | v-row]
__device__ int            g_idx32;                   // 1 if edge_index is int32
__device__ int            g_ready;                   // intra-grid flag: cursors zeroed

// ---------------------------------------------------------------- fused prep:
// block 0                      : dtype detect + zero g_cnt + release g_ready
// blocks [1, 1+scat_blocks)    : edge scatter (spin-wait on g_ready first)
// blocks [1+scat_blocks, ...)  : fp16 convert of k,v into g_kv (independent)
// Deadlock-free: block 0 + scatter blocks have the lowest block ids, so they
// are all resident in wave 1 (<< co-resident capacity). g_ready is reset by
// the gather kernel (stream-ordered after this kernel) for the next replay;
// first launch sees the .bss zero.
__global__ void ca_prep_kernel(const float* __restrict__ k,
                               const float* __restrict__ v,
                               const void* __restrict__ ei_raw,
                               int total8 /* N*HIDDEN/8 */, int N, int E,
                               int scat_blocks) {
    if (blockIdx.x == 0) {
        // ---- zero + detect role ----
        int i = threadIdx.x;
        int nsample = E < 256 ? E : 256;
        int bad = 0;
        if (i < nsample) {
            long long x = ((const long long*)ei_raw)[i];
            bad = (x < 0 || x >= (long long)N) ? 1 : 0;
        }
        int any = __syncthreads_or(bad);
        if (i == 0) g_idx32 = any;

        for (int i4 = threadIdx.x * 4; i4 < N; i4 += blockDim.x * 4) {
            if (i4 + 3 < N) *(int4*)&g_cnt[i4] = make_int4(0, 0, 0, 0);
            else { for (int t = i4; t < N; ++t) g_cnt[t] = 0; }
        }
        __syncthreads();
        __threadfence();
        if (threadIdx.x == 0) atomicExch(&g_ready, 1);
    } else if (blockIdx.x <= (unsigned)scat_blocks) {
        // ---- scatter role: 4 edges/thread ----
        if (threadIdx.x == 0) {
            while (atomicAdd(&g_ready, 0) == 0) { }
        }
        __syncthreads();
        __threadfence();

        int sb   = blockIdx.x - 1;
        int base = (sb * blockDim.x + threadIdx.x) * 4;
        if (base >= E) return;
        int n = E - base; if (n > 4) n = 4;

        int src[4], dst[4];
        if (g_idx32) {
            const int* ei = (const int*)ei_raw;
            #pragma unroll
            for (int i = 0; i < 4; ++i) {
                if (i < n) { src[i] = ei[base + i]; dst[i] = ei[E + base + i]; }
            }
        } else {
            const long long* ei = (const long long*)ei_raw;
            #pragma unroll
            for (int i = 0; i < 4; ++i) {
                if (i < n) { src[i] = (int)ei[base + i]; dst[i] = (int)ei[E + base + i]; }
            }
        }
        #pragma unroll
        for (int i = 0; i < 4; ++i) {
            if (i < n &&
                (unsigned)src[i] < (unsigned)N && (unsigned)dst[i] < (unsigned)N) {
                int pos = atomicAdd(&g_cnt[dst[i]], 1);
                if (pos < MAX_DEG)
                    g_srcs[dst[i] * MAX_DEG + pos] = (unsigned short)src[i];
            }
        }
    } else {
        // ---- convert role ----
        int cb = blockIdx.x - 1 - scat_blocks;
        int t  = cb * blockDim.x + threadIdx.x;
        if (t >= total8) return;
        int p    = t * 8;                 // linear float index into k / v
        int node = p >> 8;                // / HIDDEN
        int idx  = p & (HIDDEN - 1);

        float4 ka = *(const float4*)(k + p);
        float4 kb = *(const float4*)(k + p + 4);
        float4 va = *(const float4*)(v + p);
        float4 vb = *(const float4*)(v + p + 4);

        __half2 kh[4], vh[4];
        kh[0] = __floats2half2_rn(ka.x, ka.y);
        kh[1] = __floats2half2_rn(ka.z, ka.w);
        kh[2] = __floats2half2_rn(kb.x, kb.y);
        kh[3] = __floats2half2_rn(kb.z, kb.w);
        vh[0] = __floats2half2_rn(va.x, va.y);
        vh[1] = __floats2half2_rn(va.z, va.w);
        vh[2] = __floats2half2_rn(vb.x, vb.y);
        vh[3] = __floats2half2_rn(vb.z, vb.w);

        __half* row = g_kv + (size_t)node * KV_ROW;
        *(uint4*)(row + idx)          = *(const uint4*)kh;
        *(uint4*)(row + HIDDEN + idx) = *(const uint4*)vh;
    }
}

// ---------------------------------------------------------------- per-edge fp16 math
__device__ __forceinline__ void ca_edge_math(uint4 kb, uint4 vb,
                                             float4 q0, float4 q1,
                                             float& a0, float& a1, float& a2, float& a3,
                                             float& a4, float& a5, float& a6, float& a7,
                                             float& zsum) {
    const __half2* kh = (const __half2*)&kb;
    const __half2* vh = (const __half2*)&vb;
    float2 k0 = __half22float2(kh[0]);
    float2 k1 = __half22float2(kh[1]);
    float2 k2 = __half22float2(kh[2]);
    float2 k3 = __half22float2(kh[3]);

    float d = k0.x*q0.x + k0.y*q0.y + k1.x*q0.z + k1.y*q0.w
            + k2.x*q1.x + k2.y*q1.y + k3.x*q1.z + k3.y*q1.w;
    d += __shfl_xor_sync(0xffffffffu, d, 1);
    d += __shfl_xor_sync(0xffffffffu, d, 2);

    float s = __expf(fminf(5.0f, fmaxf(-5.0f, d * INV_SCALE)));

    float2 v0 = __half22float2(vh[0]);
    float2 v1 = __half22float2(vh[1]);
    float2 v2 = __half22float2(vh[2]);
    float2 v3 = __half22float2(vh[3]);
    a0 += v0.x*s; a1 += v0.y*s; a2 += v1.x*s; a3 += v1.y*s;
    a4 += v2.x*s; a5 += v2.y*s; a6 += v3.x*s; a7 += v3.y*s;
    zsum += s;
}

// ---------------------------------------------------------------- gather + normalize
// Hot path identical to R9. Block 0 / thread 0 additionally resets g_ready
// for the next replay (single store, outside the per-warp hot loop).
__global__ void ca_gather_kernel(const float* __restrict__ q,
                                 float* __restrict__ out,
                                 int N) {
    if (blockIdx.x == 0 && threadIdx.x == 0) g_ready = 0;

    int node = blockIdx.x * (blockDim.x >> 5) + (threadIdx.x >> 5);
    if (node >= N) return;
    int lane = threadIdx.x & 31;
    int head = lane >> 2;
    int sub  = lane & 3;
    int off  = head * HEAD_DIM + sub * 8;

    const float4* qp = (const float4*)(q + (size_t)node * HIDDEN + off);
    float4 q0 = qp[0], q1 = qp[1];

    float a0=0,a1=0,a2=0,a3=0,a4=0,a5=0,a6=0,a7=0;
    float zsum = 0.0f;

    int deg = g_cnt[node];
    if (deg > MAX_DEG) deg = MAX_DEG;
    const unsigned short* adj = &g_srcs[node * MAX_DEG];
    int j = 0;

    for (; j + 3 < deg; j += 4) {
        ushort4 s4 = *(const ushort4*)(adj + j);   // row base 256B-aligned, j%4==0
        const __half* r0 = g_kv + (size_t)s4.x * KV_ROW + off;
        const __half* r1 = g_kv + (size_t)s4.y * KV_ROW + off;
        const __half* r2 = g_kv + (size_t)s4.z * KV_ROW + off;
        const __half* r3 = g_kv + (size_t)s4.w * KV_ROW + off;
        uint4 kb0 = *(const uint4*)(r0);
        uint4 vb0 = *(const uint4*)(r0 + HIDDEN);
        uint4 kb1 = *(const uint4*)(r1);
        uint4 vb1 = *(const uint4*)(r1 + HIDDEN);
        uint4 kb2 = *(const uint4*)(r2);
        uint4 vb2 = *(const uint4*)(r2 + HIDDEN);
        uint4 kb3 = *(const uint4*)(r3);
        uint4 vb3 = *(const uint4*)(r3 + HIDDEN);

        ca_edge_math(kb0, vb0, q0, q1, a0,a1,a2,a3,a4,a5,a6,a7, zsum);
        ca_edge_math(kb1, vb1, q0, q1, a0,a1,a2,a3,a4,a5,a6,a7, zsum);
        ca_edge_math(kb2, vb2, q0, q1, a0,a1,a2,a3,a4,a5,a6,a7, zsum);
        ca_edge_math(kb3, vb3, q0, q1, a0,a1,a2,a3,a4,a5,a6,a7, zsum);
    }
    for (; j < deg; ++j) {
        int s = adj[j];
        const __half* r = g_kv + (size_t)s * KV_ROW + off;
        uint4 kb = *(const uint4*)(r);
        uint4 vb = *(const uint4*)(r + HIDDEN);
        ca_edge_math(kb, vb, q0, q1, a0,a1,a2,a3,a4,a5,a6,a7, zsum);
    }

    float zinv = 1.0f / (zsum + 1e-6f);
    float4 o0 = make_float4(a0*zinv, a1*zinv, a2*zinv, a3*zinv);
    float4 o1 = make_float4(a4*zinv, a5*zinv, a6*zinv, a7*zinv);
    float4* op = (float4*)(out + (size_t)node * HIDDEN + off);
    op[0] = o0;
    op[1] = o1;
}

extern "C" void kernel_launch(void* const* d_in, const int* in_sizes, int n_in,
                              void* d_out, int out_size) {
    const float* q  = (const float*)d_in[0];
    const float* k  = (const float*)d_in[1];
    const float* v  = (const float*)d_in[2];
    const void*  ei = d_in[3];
    float* out = (float*)d_out;

    int N = in_sizes[0] / HIDDEN;
    int E = in_sizes[3] / 2;

    // B: fused zero+detect / scatter / convert
    {
        int total8      = N * HIDDEN / 8;
        int conv_blocks = (total8 + 255) / 256;
        int scat_thr    = (E + 3) / 4;
        int scat_blocks = (scat_thr + 255) / 256;
        ca_prep_kernel<<<1 + scat_blocks + conv_blocks, 256>>>(k, v, ei,
                                                               total8, N, E,
                                                               scat_blocks);
    }
    // C: gather + normalize
    {
        int warps_per_block = 8;
        int threads = warps_per_block * 32;
        int blocks = (N + warps_per_block - 1) / warps_per_block;
        ca_gather_kernel<<<blocks, threads>>>(q, out, N);
    }
}

// round 12
// speedup vs baseline: 1.0546x; 1.0085x over previous
#include <cuda_runtime.h>
#include <cuda_fp16.h>

#define HIDDEN    256
#define NUM_HEADS 8
#define HEAD_DIM  32
#define MAX_N     20000
#define MAX_E     320000
#define MAX_DEG   128
#define KV_ROW    512                      /* 256 k-halves + 256 v-halves */
#define INV_SCALE 0.17677669529663687f     /* 1/sqrt(32) */

// Scratch (alloc-free rule: __device__ globals)
__device__ int            g_cnt[MAX_N];              // per-node fill cursor / degree
__device__ unsigned short g_srcs[MAX_N * MAX_DEG];   // bucketed adjacency (src < 65536)
__device__ __half         g_kv[MAX_N * KV_ROW];      // interleaved fp16 [k-row | v-row]
__device__ int            g_idx32;                   // 1 if edge_index is int32
__device__ int            g_ready;                   // intra-grid flag: cursors zeroed

// ---------------------------------------------------------------- f32x2 packed helpers
__device__ __forceinline__ unsigned long long pk2(float lo, float hi) {
    unsigned long long r;
    asm("mov.b64 %0, {%1, %2};" : "=l"(r) : "f"(lo), "f"(hi));
    return r;
}
__device__ __forceinline__ void unpk2(unsigned long long p, float& lo, float& hi) {
    asm("mov.b64 {%0, %1}, %2;" : "=f"(lo), "=f"(hi) : "l"(p));
}
__device__ __forceinline__ unsigned long long fma2(unsigned long long a,
                                                   unsigned long long b,
                                                   unsigned long long c) {
    unsigned long long d;
    asm("fma.rn.f32x2 %0, %1, %2, %3;" : "=l"(d) : "l"(a), "l"(b), "l"(c));
    return d;
}
__device__ __forceinline__ unsigned long long mul2(unsigned long long a,
                                                   unsigned long long b) {
    unsigned long long d;
    asm("mul.rn.f32x2 %0, %1, %2;" : "=l"(d) : "l"(a), "l"(b));
    return d;
}

// ---------------------------------------------------------------- fused prep (R11, unchanged):
// block 0                      : dtype detect + zero g_cnt + release g_ready
// blocks [1, 1+scat_blocks)    : edge scatter (spin-wait on g_ready first)
// blocks [1+scat_blocks, ...)  : fp16 convert of k,v into g_kv (independent)
__global__ void ca_prep_kernel(const float* __restrict__ k,
                               const float* __restrict__ v,
                               const void* __restrict__ ei_raw,
                               int total8 /* N*HIDDEN/8 */, int N, int E,
                               int scat_blocks) {
    if (blockIdx.x == 0) {
        int i = threadIdx.x;
        int nsample = E < 256 ? E : 256;
        int bad = 0;
        if (i < nsample) {
            long long x = ((const long long*)ei_raw)[i];
            bad = (x < 0 || x >= (long long)N) ? 1 : 0;
        }
        int any = __syncthreads_or(bad);
        if (i == 0) g_idx32 = any;

        for (int i4 = threadIdx.x * 4; i4 < N; i4 += blockDim.x * 4) {
            if (i4 + 3 < N) *(int4*)&g_cnt[i4] = make_int4(0, 0, 0, 0);
            else { for (int t = i4; t < N; ++t) g_cnt[t] = 0; }
        }
        __syncthreads();
        __threadfence();
        if (threadIdx.x == 0) atomicExch(&g_ready, 1);
    } else if (blockIdx.x <= (unsigned)scat_blocks) {
        if (threadIdx.x == 0) {
            while (atomicAdd(&g_ready, 0) == 0) { }
        }
        __syncthreads();
        __threadfence();

        int sb   = blockIdx.x - 1;
        int base = (sb * blockDim.x + threadIdx.x) * 4;
        if (base >= E) return;
        int n = E - base; if (n > 4) n = 4;

        int src[4], dst[4];
        if (g_idx32) {
            const int* ei = (const int*)ei_raw;
            #pragma unroll
            for (int i = 0; i < 4; ++i) {
                if (i < n) { src[i] = ei[base + i]; dst[i] = ei[E + base + i]; }
            }
        } else {
            const long long* ei = (const long long*)ei_raw;
            #pragma unroll
            for (int i = 0; i < 4; ++i) {
                if (i < n) { src[i] = (int)ei[base + i]; dst[i] = (int)ei[E + base + i]; }
            }
        }
        #pragma unroll
        for (int i = 0; i < 4; ++i) {
            if (i < n &&
                (unsigned)src[i] < (unsigned)N && (unsigned)dst[i] < (unsigned)N) {
                int pos = atomicAdd(&g_cnt[dst[i]], 1);
                if (pos < MAX_DEG)
                    g_srcs[dst[i] * MAX_DEG + pos] = (unsigned short)src[i];
            }
        }
    } else {
        int cb = blockIdx.x - 1 - scat_blocks;
        int t  = cb * blockDim.x + threadIdx.x;
        if (t >= total8) return;
        int p    = t * 8;
        int node = p >> 8;
        int idx  = p & (HIDDEN - 1);

        float4 ka = *(const float4*)(k + p);
        float4 kb = *(const float4*)(k + p + 4);
        float4 va = *(const float4*)(v + p);
        float4 vb = *(const float4*)(v + p + 4);

        __half2 kh[4], vh[4];
        kh[0] = __floats2half2_rn(ka.x, ka.y);
        kh[1] = __floats2half2_rn(ka.z, ka.w);
        kh[2] = __floats2half2_rn(kb.x, kb.y);
        kh[3] = __floats2half2_rn(kb.z, kb.w);
        vh[0] = __floats2half2_rn(va.x, va.y);
        vh[1] = __floats2half2_rn(va.z, va.w);
        vh[2] = __floats2half2_rn(vb.x, vb.y);
        vh[3] = __floats2half2_rn(vb.z, vb.w);

        __half* row = g_kv + (size_t)node * KV_ROW;
        *(uint4*)(row + idx)          = *(const uint4*)kh;
        *(uint4*)(row + HIDDEN + idx) = *(const uint4*)vh;
    }
}

// ---------------------------------------------------------------- per-edge math (f32x2)
// qq[4]/acc[4] are packed f32x2 pairs. Same fp32 numerics as the scalar version.
__device__ __forceinline__ void ca_edge_math(uint4 kb, uint4 vb,
                                             const unsigned long long* qq,
                                             unsigned long long* acc,
                                             float& zsum) {
    const __half2* kh = (const __half2*)&kb;
    const __half2* vh = (const __half2*)&vb;

    float2 k0 = __half22float2(kh[0]);
    float2 k1 = __half22float2(kh[1]);
    float2 k2 = __half22float2(kh[2]);
    float2 k3 = __half22float2(kh[3]);

    unsigned long long d2 = mul2(pk2(k0.x, k0.y), qq[0]);
    d2 = fma2(pk2(k1.x, k1.y), qq[1], d2);
    d2 = fma2(pk2(k2.x, k2.y), qq[2], d2);
    d2 = fma2(pk2(k3.x, k3.y), qq[3], d2);
    float dlo, dhi;
    unpk2(d2, dlo, dhi);
    float d = dlo + dhi;
    d += __shfl_xor_sync(0xffffffffu, d, 1);
    d += __shfl_xor_sync(0xffffffffu, d, 2);

    float s = __expf(fminf(5.0f, fmaxf(-5.0f, d * INV_SCALE)));
    unsigned long long ss = pk2(s, s);

    float2 v0 = __half22float2(vh[0]);
    float2 v1 = __half22float2(vh[1]);
    float2 v2 = __half22float2(vh[2]);
    float2 v3 = __half22float2(vh[3]);
    acc[0] = fma2(pk2(v0.x, v0.y), ss, acc[0]);
    acc[1] = fma2(pk2(v1.x, v1.y), ss, acc[1]);
    acc[2] = fma2(pk2(v2.x, v2.y), ss, acc[2]);
    acc[3] = fma2(pk2(v3.x, v3.y), ss, acc[3]);
    zsum += s;
}

// ---------------------------------------------------------------- gather + normalize
// One warp per node; lane: head = lane>>2, sub = lane&3, 8 elems per lane.
// fp16 kv rows; 4-edge unroll; f32x2 packed math; 128-thread blocks.
__global__ void __launch_bounds__(128)
ca_gather_kernel(const float* __restrict__ q,
                 float* __restrict__ out,
                 int N) {
    if (blockIdx.x == 0 && threadIdx.x == 0) g_ready = 0;

    int node = blockIdx.x * (blockDim.x >> 5) + (threadIdx.x >> 5);
    if (node >= N) return;
    int lane = threadIdx.x & 31;
    int head = lane >> 2;
    int sub  = lane & 3;
    int off  = head * HEAD_DIM + sub * 8;

    const float4* qp = (const float4*)(q + (size_t)node * HIDDEN + off);
    float4 qa = qp[0], qb = qp[1];
    unsigned long long qq[4];
    qq[0] = pk2(qa.x, qa.y);
    qq[1] = pk2(qa.z, qa.w);
    qq[2] = pk2(qb.x, qb.y);
    qq[3] = pk2(qb.z, qb.w);

    unsigned long long acc[4];
    acc[0] = acc[1] = acc[2] = acc[3] = pk2(0.0f, 0.0f);
    float zsum = 0.0f;

    int deg = g_cnt[node];
    if (deg > MAX_DEG) deg = MAX_DEG;
    const unsigned short* adj = &g_srcs[node * MAX_DEG];
    int j = 0;

    for (; j + 3 < deg; j += 4) {
        ushort4 s4 = *(const ushort4*)(adj + j);   // row base 256B-aligned, j%4==0
        const __half* r0 = g_kv + (size_t)s4.x * KV_ROW + off;
        const __half* r1 = g_kv + (size_t)s4.y * KV_ROW + off;
        const __half* r2 = g_kv + (size_t)s4.z * KV_ROW + off;
        const __half* r3 = g_kv + (size_t)s4.w * KV_ROW + off;
        uint4 kb0 = *(const uint4*)(r0);
        uint4 vb0 = *(const uint4*)(r0 + HIDDEN);
        uint4 kb1 = *(const uint4*)(r1);
        uint4 vb1 = *(const uint4*)(r1 + HIDDEN);
        uint4 kb2 = *(const uint4*)(r2);
        uint4 vb2 = *(const uint4*)(r2 + HIDDEN);
        uint4 kb3 = *(const uint4*)(r3);
        uint4 vb3 = *(const uint4*)(r3 + HIDDEN);

        ca_edge_math(kb0, vb0, qq, acc, zsum);
        ca_edge_math(kb1, vb1, qq, acc, zsum);
        ca_edge_math(kb2, vb2, qq, acc, zsum);
        ca_edge_math(kb3, vb3, qq, acc, zsum);
    }
    for (; j < deg; ++j) {
        int s = adj[j];
        const __half* r = g_kv + (size_t)s * KV_ROW + off;
        uint4 kb = *(const uint4*)(r);
        uint4 vb = *(const uint4*)(r + HIDDEN);
        ca_edge_math(kb, vb, qq, acc, zsum);
    }

    float zinv = 1.0f / (zsum + 1e-6f);
    float a0,a1,a2,a3,a4,a5,a6,a7;
    unpk2(acc[0], a0, a1);
    unpk2(acc[1], a2, a3);
    unpk2(acc[2], a4, a5);
    unpk2(acc[3], a6, a7);
    float4 o0 = make_float4(a0*zinv, a1*zinv, a2*zinv, a3*zinv);
    float4 o1 = make_float4(a4*zinv, a5*zinv, a6*zinv, a7*zinv);
    float4* op = (float4*)(out + (size_t)node * HIDDEN + off);
    op[0] = o0;
    op[1] = o1;
}

extern "C" void kernel_launch(void* const* d_in, const int* in_sizes, int n_in,
                              void* d_out, int out_size) {
    const float* q  = (const float*)d_in[0];
    const float* k  = (const float*)d_in[1];
    const float* v  = (const float*)d_in[2];
    const void*  ei = d_in[3];
    float* out = (float*)d_out;

    int N = in_sizes[0] / HIDDEN;
    int E = in_sizes[3] / 2;

    // B: fused zero+detect / scatter / convert
    {
        int total8      = N * HIDDEN / 8;
        int conv_blocks = (total8 + 255) / 256;
        int scat_thr    = (E + 3) / 4;
        int scat_blocks = (scat_thr + 255) / 256;
        ca_prep_kernel<<<1 + scat_blocks + conv_blocks, 256>>>(k, v, ei,
                                                               total8, N, E,
                                                               scat_blocks);
    }
    // C: gather + normalize (128-thread blocks = 4 warps)
    {
        int warps_per_block = 4;
        int threads = warps_per_block * 32;
        int blocks = (N + warps_per_block - 1) / warps_per_block;
        ca_gather_kernel<<<blocks, threads>>>(q, out, N);
    }
}